// round 14
// baseline (speedup 1.0000x reference)
#include <cuda_runtime.h>

#define Z_DIM 256
#define A_DIM 512
#define B_DIM 64
#define TPB 256
#define TILE_ROWS 16                       // 16 rows x 64 cols = 256 float4
#define NTILES (A_DIM / TILE_ROWS)         // 32
#define PER_Z 266432
#define OFF_H1 0
#define OFF_H2 64
#define OFF_H3 4160
#define OFF_H4 4224
#define OFF_H5 4288
#define BH 32                              // gram rows per CTA (half)

__global__ __launch_bounds__(TPB) void perm_inv_fused_half(
    const float* __restrict__ x, float* __restrict__ out)
{
    __shared__ float4 xs[2][256];              // double-buffered 16-row tile (8 KB)
    __shared__ float  gram_s[BH * B_DIM];      // 8 KB (this CTA's 32 gram rows)
    __shared__ float  cs_s[B_DIM];
    __shared__ float  ss_s[B_DIM];

    const int half = blockIdx.x;               // 0 or 1: gram rows [32h, 32h+32)
    const int z    = blockIdx.y;
    const int t    = threadIdx.x;
    const int tx   = t & 15;                   // c group: cols c0 = 4*tx (global, all 64)
    const int ty   = t >> 4;                   // local b group: b_local0 = 2*ty

    const float4* __restrict__ xin =
        (const float4*)(x + (size_t)z * A_DIM * B_DIM);   // 8192 float4 per z

    float acc[2][4];
    #pragma unroll
    for (int i = 0; i < 2; ++i)
        #pragma unroll
        for (int j = 0; j < 4; ++j) acc[i][j] = 0.f;

    float4 cs4 = make_float4(0.f, 0.f, 0.f, 0.f);
    float4 ss4 = make_float4(0.f, 0.f, 0.f, 0.f);

    // ---- prologue: tile 0 ----
    {
        float4 g = xin[t];
        xs[0][t] = g;
        cs4.x += g.x; cs4.y += g.y; cs4.z += g.z; cs4.w += g.w;
        ss4.x += g.x * g.x; ss4.y += g.y * g.y;
        ss4.z += g.z * g.z; ss4.w += g.w * g.w;
    }
    __syncthreads();

    // b columns this thread reads from x: global 32*half + 2*ty (+0,+1), as float2
    const int vb_f2_base = 16 * half + ty;     // float2 index within a 64-float row (32 float2)

    // ---- mainloop: half-gram accumulation, double-buffered ----
    for (int tile = 0; tile < NTILES; ++tile) {
        const int cur = tile & 1;
        float4 gn;
        const bool more = (tile + 1 < NTILES);
        if (more) gn = xin[(tile + 1) * 256 + t];   // prefetch next tile

        const float2* xs2 = (const float2*)xs[cur];
        const float4* xs4 = xs[cur];
        #pragma unroll
        for (int r = 0; r < TILE_ROWS; ++r) {
            float2 vb = xs2[r * 32 + vb_f2_base];   // x[r][32h+2ty .. +1]
            float4 vc = xs4[r * 16 + tx];           // x[r][4tx .. +3]
            acc[0][0] += vb.x * vc.x; acc[0][1] += vb.x * vc.y;
            acc[0][2] += vb.x * vc.z; acc[0][3] += vb.x * vc.w;
            acc[1][0] += vb.y * vc.x; acc[1][1] += vb.y * vc.y;
            acc[1][2] += vb.y * vc.z; acc[1][3] += vb.y * vc.w;
        }

        if (more) {
            xs[cur ^ 1][t] = gn;                    // other buffer: no race
            cs4.x += gn.x; cs4.y += gn.y; cs4.z += gn.z; cs4.w += gn.w;
            ss4.x += gn.x * gn.x; ss4.y += gn.y * gn.y;
            ss4.z += gn.z * gn.z; ss4.w += gn.w * gn.w;
        }
        __syncthreads();
    }

    // ---- reduce cs / ssq partials (reuse xs buffers) ----
    xs[0][t] = cs4;
    xs[1][t] = ss4;

    // ---- gram half -> smem: rows b_local = 2*ty + i, cols 4*tx + j ----
    #pragma unroll
    for (int i = 0; i < 2; ++i)
        #pragma unroll
        for (int j = 0; j < 4; ++j)
            gram_s[(2 * ty + i) * B_DIM + (4 * tx + j)] = acc[i][j];
    __syncthreads();

    if (t < 16) {
        float4 sc = make_float4(0.f, 0.f, 0.f, 0.f);
        float4 sq = make_float4(0.f, 0.f, 0.f, 0.f);
        #pragma unroll
        for (int k = 0; k < 16; ++k) {
            float4 a = xs[0][k * 16 + t];
            float4 b = xs[1][k * 16 + t];
            sc.x += a.x; sc.y += a.y; sc.z += a.z; sc.w += a.w;
            sq.x += b.x; sq.y += b.y; sq.z += b.z; sq.w += b.w;
        }
        ((float4*)cs_s)[t] = sc;
        ((float4*)ss_s)[t] = sq;
    }
    __syncthreads();

    float* __restrict__ oz = out + (size_t)z * PER_Z;

    // ---- h2 half: gram rows [32h, 32h+32) = 2048 floats = 512 float4 ----
    {
        float4* o2 = (float4*)(oz + OFF_H2 + half * (BH * B_DIM));
        const float4* g4 = (const float4*)gram_s;
        __stcs(&o2[t], g4[t]);
        __stcs(&o2[t + 256], g4[t + 256]);
    }

    // ---- h1, h3, h4 (half 0 only) ----
    if (half == 0 && t < B_DIM) {
        float c = cs_s[t];
        oz[OFF_H1 + t] = c;
        oz[OFF_H3 + t] = ss_s[t];
        oz[OFF_H4 + t] = c * c;
    }

    // ---- h5 half: out[b*4096 + c*64 + d] = gram[b,c]*cs[d], b in this half ----
    // Half block = 32*64*64 floats = 32768 float4. idx4 = it*256 + t:
    // d-group = t&15 (constant per thread, cs4 hoisted), bc_local = it*16 + ty.
    {
        const float4 c4 = ((const float4*)cs_s)[tx];
        float4* o5 = (float4*)(oz + OFF_H5 + half * (BH * B_DIM * B_DIM));
        #pragma unroll 4
        for (int it = 0; it < 128; ++it) {
            float gv = gram_s[ty + it * 16];        // gram_s[bc_local], warp-broadcast
            float4 v = make_float4(gv * c4.x, gv * c4.y, gv * c4.z, gv * c4.w);
            __stcs(&o5[it * 256 + t], v);
        }
    }
}

extern "C" void kernel_launch(void* const* d_in, const int* in_sizes, int n_in,
                              void* d_out, int out_size)
{
    (void)in_sizes; (void)n_in; (void)out_size;
    const float* x = (const float*)d_in[0];
    float* out = (float*)d_out;
    dim3 grid(2, Z_DIM);                       // pairs adjacent -> L2 reuse of x[z]
    perm_inv_fused_half<<<grid, TPB>>>(x, out);
}

// round 15
// speedup vs baseline: 1.3366x; 1.3366x over previous
#include <cuda_runtime.h>

#define Z_DIM 256
#define A_DIM 512
#define B_DIM 64
#define TPB 256
#define TILE_ROWS 16                       // 16 rows x 64 cols = 256 float4
#define NTILES (A_DIM / TILE_ROWS)         // 32
#define PER_Z 266432
#define OFF_H1 0
#define OFF_H2 64
#define OFF_H3 4160
#define OFF_H4 4224
#define OFF_H5 4288

typedef unsigned long long u64;

// ---- packed f32x2 helpers (sm_100+ PTX; ptxas never emits these from C++) ----
__device__ __forceinline__ u64 ffma2(u64 a, u64 b, u64 c) {
    u64 d;
    asm("fma.rn.f32x2 %0, %1, %2, %3;" : "=l"(d) : "l"(a), "l"(b), "l"(c));
    return d;
}
__device__ __forceinline__ u64 fadd2(u64 a, u64 b) {
    u64 d;
    asm("add.rn.f32x2 %0, %1, %2;" : "=l"(d) : "l"(a), "l"(b));
    return d;
}
__device__ __forceinline__ u64 dup2(float s) {
    u64 d;
    asm("mov.b64 %0, {%1, %1};" : "=l"(d) : "f"(s));
    return d;
}
__device__ __forceinline__ float2 unpack2(u64 a) {
    float2 u;
    asm("mov.b64 {%0, %1}, %2;" : "=f"(u.x), "=f"(u.y) : "l"(a));
    return u;
}

__global__ __launch_bounds__(TPB) void perm_inv_fused(
    const float* __restrict__ x, float* __restrict__ out)
{
    __shared__ float4 xs[2][256];             // double-buffered 16-row tile (8 KB)
    __shared__ float  gram_s[B_DIM * B_DIM];  // 16 KB
    __shared__ float  cs_s[B_DIM];
    __shared__ float  ss_s[B_DIM];

    const int z  = blockIdx.x;
    const int t  = threadIdx.x;
    const int tx = t & 15;                    // c tile group (cols c0 = 4*tx)
    const int ty = t >> 4;                    // b tile group (rows b0 = 4*ty)

    const ulonglong2* __restrict__ xin =
        (const ulonglong2*)(x + (size_t)z * A_DIM * B_DIM);  // 8192 x 16B per z

    // acc2[i][jh] = packed pair (gram[b0+i][c0+2jh], gram[b0+i][c0+2jh+1])
    u64 acc2[4][2];
    #pragma unroll
    for (int i = 0; i < 4; ++i) { acc2[i][0] = 0ull; acc2[i][1] = 0ull; }

    u64 cs2[2] = {0ull, 0ull};                // packed column-sum partials
    u64 ss2[2] = {0ull, 0ull};                // packed sum-of-squares partials

    // ---- prologue: tile 0 ----
    {
        ulonglong2 g = xin[t];
        ((ulonglong2*)xs[0])[t] = g;
        cs2[0] = fadd2(cs2[0], g.x);  cs2[1] = fadd2(cs2[1], g.y);
        ss2[0] = ffma2(g.x, g.x, ss2[0]);  ss2[1] = ffma2(g.y, g.y, ss2[1]);
    }
    __syncthreads();

    // ---- mainloop: gram accumulation, double-buffered, FFMA2 inner ----
    for (int tile = 0; tile < NTILES; ++tile) {
        const int cur = tile & 1;
        ulonglong2 gn;
        const bool more = (tile + 1 < NTILES);
        if (more) gn = xin[(tile + 1) * 256 + t];   // prefetch next tile

        const float4*     xs4 = xs[cur];
        const ulonglong2* xsp = (const ulonglong2*)xs[cur];
        #pragma unroll
        for (int r = 0; r < TILE_ROWS; ++r) {
            float4     vb = xs4[r * 16 + ty];       // x[r][4ty .. +3]
            ulonglong2 vc = xsp[r * 16 + tx];       // pairs (c0,c1),(c2,c3)
            u64 b0 = dup2(vb.x), b1 = dup2(vb.y), b2 = dup2(vb.z), b3 = dup2(vb.w);
            acc2[0][0] = ffma2(b0, vc.x, acc2[0][0]);
            acc2[0][1] = ffma2(b0, vc.y, acc2[0][1]);
            acc2[1][0] = ffma2(b1, vc.x, acc2[1][0]);
            acc2[1][1] = ffma2(b1, vc.y, acc2[1][1]);
            acc2[2][0] = ffma2(b2, vc.x, acc2[2][0]);
            acc2[2][1] = ffma2(b2, vc.y, acc2[2][1]);
            acc2[3][0] = ffma2(b3, vc.x, acc2[3][0]);
            acc2[3][1] = ffma2(b3, vc.y, acc2[3][1]);
        }

        if (more) {
            ((ulonglong2*)xs[cur ^ 1])[t] = gn;     // other buffer: no race
            cs2[0] = fadd2(cs2[0], gn.x);  cs2[1] = fadd2(cs2[1], gn.y);
            ss2[0] = ffma2(gn.x, gn.x, ss2[0]);  ss2[1] = ffma2(gn.y, gn.y, ss2[1]);
        }
        __syncthreads();
    }

    // ---- park cs / ssq partials in the xs buffers ----
    {
        ulonglong2 pc; pc.x = cs2[0]; pc.y = cs2[1];
        ulonglong2 ps; ps.x = ss2[0]; ps.y = ss2[1];
        ((ulonglong2*)xs[0])[t] = pc;
        ((ulonglong2*)xs[1])[t] = ps;
    }

    // ---- gram -> smem ----
    #pragma unroll
    for (int i = 0; i < 4; ++i) {
        float2* grow = (float2*)&gram_s[(ty * 4 + i) * B_DIM + tx * 4];
        grow[0] = unpack2(acc2[i][0]);
        grow[1] = unpack2(acc2[i][1]);
    }
    __syncthreads();

    if (t < 16) {
        u64 sc[2] = {0ull, 0ull};
        u64 sq[2] = {0ull, 0ull};
        #pragma unroll
        for (int k = 0; k < 16; ++k) {
            ulonglong2 a = ((const ulonglong2*)xs[0])[k * 16 + t];
            ulonglong2 b = ((const ulonglong2*)xs[1])[k * 16 + t];
            sc[0] = fadd2(sc[0], a.x);  sc[1] = fadd2(sc[1], a.y);
            sq[0] = fadd2(sq[0], b.x);  sq[1] = fadd2(sq[1], b.y);
        }
        ulonglong2 oc; oc.x = sc[0]; oc.y = sc[1];
        ulonglong2 oq; oq.x = sq[0]; oq.y = sq[1];
        ((ulonglong2*)cs_s)[t] = oc;
        ((ulonglong2*)ss_s)[t] = oq;
    }
    __syncthreads();

    float* __restrict__ oz = out + (size_t)z * PER_Z;

    // ---- h2: gram, coalesced float4 copy (4096 floats = 1024 float4) ----
    {
        float4* o2 = (float4*)(oz + OFF_H2);
        const float4* g4 = (const float4*)gram_s;
        #pragma unroll
        for (int i = 0; i < 4; ++i) {
            float4 v = g4[t + i * 256];
            __stcs(&o2[t + i * 256], v);
        }
    }

    // ---- h1, h3, h4 ----
    if (t < B_DIM) {
        float c = cs_s[t];
        oz[OFF_H1 + t] = c;
        oz[OFF_H3 + t] = ss_s[t];
        oz[OFF_H4 + t] = c * c;
    }

    // ---- h5: out[b*4096 + c*64 + d] = gram[b,c] * cs[d] ----
    // float4 index idx4 = it*256 + t; d-group = t&15 (constant per thread),
    // bc = it*16 + (t>>4). cs float4 hoisted into registers.
    {
        const float4 c4 = ((const float4*)cs_s)[tx];
        float4* o5 = (float4*)(oz + OFF_H5);
        const int bc0 = ty;                // t >> 4
        #pragma unroll 4
        for (int it = 0; it < 256; ++it) {
            float gv = gram_s[bc0 + it * 16];
            float4 v = make_float4(gv * c4.x, gv * c4.y, gv * c4.z, gv * c4.w);
            __stcs(&o5[it * 256 + t], v);
        }
    }
}

extern "C" void kernel_launch(void* const* d_in, const int* in_sizes, int n_in,
                              void* d_out, int out_size)
{
    (void)in_sizes; (void)n_in; (void)out_size;
    const float* x = (const float*)d_in[0];
    float* out = (float*)d_out;
    perm_inv_fused<<<Z_DIM, TPB>>>(x, out);
}